// round 15
// baseline (speedup 1.0000x reference)
#include <cuda_runtime.h>
#include <cuda_bf16.h>
#include <cstdint>

// Problem constants
#define Qn 4
#define Kc 2048
#define Dd 256
#define Bb 8
#define Nn 8192
#define NTOK (Bb * Nn)        // 65536 tokens
#define MCHUNK (Nn / Qn)      // 2048 tokens per (b, q) chunk

// Screening GEMM tiling (mma.m16n8k16 bf16 -> f32)
#define TM 128                // tokens per block
#define TILE_N 16             // codes per tile (2 n8-blocks)
#define NTILE (Kc / TILE_N)   // 128 tiles
#define KSTEPS (Dd / 16)      // 16 k-steps
#define NSLOT 4               // B ring slots; prefetch distance 3 (commit groups)

#define LDMAB 264             // padded leading dim (bf16): 528B rows, conflict-free ldsm
#define ROWB  (LDMAB * 2)     // 528 bytes

#define TAU 2e-3f             // certification margin (~7 sigma of bf16 screen noise)
#define FROWB 1040            // fixup smem row stride (bytes)

// SMEM layout (bytes)
#define CNT_OFF    0                          // int s_nfix, s_ndeep (8 B)
#define A_OFF      128
#define A_BYTES    (TM * ROWB)                // 67584
#define B_BYTES    (TILE_N * ROWB)            // 8448
#define BBASE_OFF  (A_OFF + A_BYTES)          // 67712
#define SMEM_TOTAL (BBASE_OFF + NSLOT * B_BYTES)   // 101504 => 2 blocks/SM
// Post-loop reuse (mainloop data dead):
//   fix e-rows: A_OFF, 64 x FROWB = 66560 <= 67584
//   fix x-rows: BBASE_OFF, 8 x FROWB = 8320 <= 8448
//   scratch in slots 1..3 (25344 B): BC 512 | FIXTOK 512 | DEEP 512 |
//                                    TOP8 4096 | RV 1024 | RI 1024 = 7680
#define BC_OFF     (BBASE_OFF + B_BYTES)
#define FIXTOK_OFF (BC_OFF + 512)
#define DEEP_OFF   (FIXTOK_OFF + 512)
#define TOP8_OFF   (DEEP_OFF + 512)
#define RV_OFF     (TOP8_OFF + 4096)
#define RI_OFF     (RV_OFF + 1024)

// Global scratch (static; no allocs)
__device__ float         g_xn[NTOK * Dd];        // normalized x, fp32 (exact rescore)
__device__ float         g_en[Qn * Kc * Dd];     // normalized embed, fp32 (exact rescore)
__device__ __nv_bfloat16 g_xnb[NTOK * Dd];       // bf16 screen copies
__device__ __nv_bfloat16 g_enb[Qn * Kc * Dd];

// ---------------------------------------------------------------------------
// PTX helpers
// ---------------------------------------------------------------------------
__device__ __forceinline__ void cp16(uint32_t smem_addr, const void* gptr) {
    asm volatile("cp.async.ca.shared.global [%0], [%1], 16;"
                 :: "r"(smem_addr), "l"(gptr));
}
__device__ __forceinline__ void cp_commit() { asm volatile("cp.async.commit_group;"); }
template <int N>
__device__ __forceinline__ void cp_wait() { asm volatile("cp.async.wait_group %0;" :: "n"(N)); }
__device__ __forceinline__ uint32_t smem_u32(const void* p) {
    uint32_t a;
    asm("{ .reg .u64 t; cvta.to.shared.u64 t, %1; cvt.u32.u64 %0, t; }"
        : "=r"(a) : "l"(p));
    return a;
}
__device__ __forceinline__ void ldsm_x4(uint32_t addr, uint32_t& r0, uint32_t& r1,
                                        uint32_t& r2, uint32_t& r3) {
    asm volatile("ldmatrix.sync.aligned.m8n8.x4.shared.b16 {%0,%1,%2,%3}, [%4];"
                 : "=r"(r0), "=r"(r1), "=r"(r2), "=r"(r3) : "r"(addr));
}
__device__ __forceinline__ void mma16816(float* c, const uint32_t* a,
                                         uint32_t b0, uint32_t b1) {
    asm volatile(
        "mma.sync.aligned.m16n8k16.row.col.f32.bf16.bf16.f32 "
        "{%0,%1,%2,%3}, {%4,%5,%6,%7}, {%8,%9}, {%0,%1,%2,%3};"
        : "+f"(c[0]), "+f"(c[1]), "+f"(c[2]), "+f"(c[3])
        : "r"(a[0]), "r"(a[1]), "r"(a[2]), "r"(a[3]), "r"(b0), "r"(b1));
}

// ---------------------------------------------------------------------------
// Kernel 0a/0b: L2 normalize rows, EXACT reference-mimicking fp32 pipeline
// (unfused mul+add, shfl.down tree, sqrt.rn, max 1e-12, div.rn).
// DO NOT CHANGE NUMERICS. Also writes bf16 screen copies.
// ---------------------------------------------------------------------------
__global__ void l2norm_e_kernel(const float* __restrict__ embed) {
    int row  = blockIdx.x * 8 + (threadIdx.x >> 5);
    int lane = threadIdx.x & 31;
    if (row >= Qn * Kc) return;
    const float* r = embed + (size_t)row * Dd;
    float v[8];
    float s = 0.f;
#pragma unroll
    for (int i = 0; i < 8; ++i) {
        v[i] = r[lane + 32 * i];
        s = __fadd_rn(s, __fmul_rn(v[i], v[i]));
    }
#pragma unroll
    for (int o = 16; o; o >>= 1)
        s = __fadd_rn(s, __shfl_down_sync(0xffffffffu, s, o));
    float total = __shfl_sync(0xffffffffu, s, 0);
    float nf = fmaxf(__fsqrt_rn(total), 1e-12f);
#pragma unroll
    for (int i = 0; i < 8; ++i) {
        float nv = __fdiv_rn(v[i], nf);
        size_t idx = (size_t)row * Dd + lane + 32 * i;
        g_en[idx]  = nv;
        g_enb[idx] = __float2bfloat16(nv);
    }
}

__global__ void l2norm_x_kernel(const float* __restrict__ x) {
    int row  = blockIdx.x * 8 + (threadIdx.x >> 5);
    int lane = threadIdx.x & 31;
    if (row >= NTOK) return;
    const float* r = x + (size_t)row * Dd;
    float v[8];
    float s = 0.f;
#pragma unroll
    for (int i = 0; i < 8; ++i) {
        v[i] = r[lane + 32 * i];
        s = __fadd_rn(s, __fmul_rn(v[i], v[i]));
    }
#pragma unroll
    for (int o = 16; o; o >>= 1)
        s = __fadd_rn(s, __shfl_down_sync(0xffffffffu, s, o));
    float total = __shfl_sync(0xffffffffu, s, 0);
    float nf = fmaxf(__fsqrt_rn(total), 1e-12f);
#pragma unroll
    for (int i = 0; i < 8; ++i) {
        float nv = __fdiv_rn(v[i], nf);
        size_t idx = (size_t)row * Dd + lane + 32 * i;
        g_xn[idx]  = nv;
        g_xnb[idx] = __float2bfloat16(nv);
    }
}

// top-8 insertion with (value desc, index asc) ordering
__device__ __forceinline__ void top8_insert(float v, int c, float* tv, int* ti) {
#pragma unroll
    for (int p = 0; p < 8; ++p) {
        bool better = (v > tv[p]) || (v == tv[p] && c < ti[p]);
        if (better) {
            float fv = tv[p]; tv[p] = v; v = fv;
            int   fc = ti[p]; ti[p] = c; c = fc;
        }
    }
}

// ---------------------------------------------------------------------------
// Kernel 1: bf16 mma.sync screening GEMM, 4-slot B ring with prefetch
// distance 3 via cp.async commit groups (wait_group<2> per tile: the
// barrier never blocks on a freshly issued copy) + IN-BLOCK exact
// certification. 256 threads, 2 blocks/SM. Warp w owns tokens [16w,16w+16).
// Exact chain: sequential ascending-d __fmaf_rn over g_xn/g_en (bit-exact
// vs rounds 4-6). Slot-reuse safety: producer at iter nt writes slot
// (nt+3)%4 == (nt-1)%4, fully consumed by the barrier at end of iter nt-1.
// ---------------------------------------------------------------------------
__global__ void __launch_bounds__(256, 2)
pq_mma_kernel(const float* __restrict__ embed,
              float* __restrict__ out,
              long long out_size) {
    extern __shared__ char smem[];
    const uint32_t sb = smem_u32(smem);
    int*   cnt       = (int*)(smem + CNT_OFF);      // [0]=nfix, [1]=ndeep
    int*   bc        = (int*)(smem + BC_OFF);
    int*   s_fixtok  = (int*)(smem + FIXTOK_OFF);
    int*   s_deeptok = (int*)(smem + DEEP_OFF);
    int*   s_top8c   = (int*)(smem + TOP8_OFF);
    float* s_rv      = (float*)(smem + RV_OFF);
    int*   s_ri      = (int*)(smem + RI_OFF);

    const int tid  = threadIdx.x;
    const int wid  = tid >> 5;
    const int lane = tid & 31;
    const int tok0 = blockIdx.x * TM;
    const int q = (tok0 % Nn) / MCHUNK;
    const __nv_bfloat16* Eb = g_enb + (size_t)q * Kc * Dd;

    if (tid == 0) { cnt[0] = 0; cnt[1] = 0; }

    // ---- prologue: group0 = A + tile0; group1 = tile1; group2 = tile2 ----
    for (int i = tid; i < TM * 32; i += 256) {
        int row = i >> 5, seg = i & 31;
        cp16(sb + A_OFF + (uint32_t)row * ROWB + (uint32_t)seg * 16,
             g_xnb + (size_t)(tok0 + row) * Dd + seg * 8);
    }
#pragma unroll
    for (int t = 0; t < 3; ++t) {
        uint32_t dstb = sb + BBASE_OFF + t * B_BYTES;
        for (int i = tid; i < TILE_N * 32; i += 256) {
            int row = i >> 5, seg = i & 31;
            cp16(dstb + (uint32_t)row * ROWB + (uint32_t)seg * 16,
                 Eb + (size_t)(t * TILE_N + row) * Dd + seg * 8);
        }
        cp_commit();    // group t (group 0 also carries A)
    }
    cp_wait<2>();       // group0 (A + tile0) landed
    __syncthreads();

    // A ldsm per-lane base (validated mapping, rounds 9/11/13)
    const uint32_t a_base = sb + A_OFF
        + (uint32_t)(wid * 16 + ((lane >> 3) & 1) * 8 + (lane & 7)) * ROWB
        + (uint32_t)((lane >> 4) * 8) * 2;

    // B ldsm per-lane offset: groups (bn0,k0),(bn0,k8),(bn1,k0),(bn1,k8)
    const uint32_t b_lane_off =
        (uint32_t)(((lane >> 4) & 1) * 8 + (lane & 7)) * ROWB +
        (uint32_t)(((lane >> 3) & 1) * 8) * 2;

    // per-thread top-8 for two token rows: A = lane>>2, B = lane>>2 + 8
    float tvA[8], tvB[8];
    int   tiA[8], tiB[8];
#pragma unroll
    for (int k = 0; k < 8; ++k) {
        tvA[k] = -3.4e38f; tiA[k] = 0x7fffffff;
        tvB[k] = -3.4e38f; tiB[k] = 0x7fffffff;
    }
    const int cb_lane = (lane & 3) * 2;

    for (int nt = 0; nt < NTILE; ++nt) {
        // ---- producer: stage tile nt+3 into slot (nt+3)&3 (slot freed by
        //      the barrier at end of iter nt-1) ----
        if (nt + 3 < NTILE) {
            const int tile = nt + 3;
            uint32_t dstb = sb + BBASE_OFF + (uint32_t)(tile & 3) * B_BYTES;
            for (int i = tid; i < TILE_N * 32; i += 256) {
                int row = i >> 5, seg = i & 31;
                cp16(dstb + (uint32_t)row * ROWB + (uint32_t)seg * 16,
                     Eb + (size_t)(tile * TILE_N + row) * Dd + seg * 8);
            }
            cp_commit();
        }

        // ---- consumer: compute tile nt (landed: waited at end of nt-1) ----
        const uint32_t bbuf = sb + BBASE_OFF + (uint32_t)(nt & 3) * B_BYTES;

        float c[2][4];
#pragma unroll
        for (int bn = 0; bn < 2; ++bn)
#pragma unroll
            for (int e = 0; e < 4; ++e) c[bn][e] = 0.f;

#pragma unroll
        for (int ks = 0; ks < KSTEPS; ++ks) {
            uint32_t a[4];
            ldsm_x4(a_base + ks * 32, a[0], a[1], a[2], a[3]);
            uint32_t b0, b1, b2, b3;
            ldsm_x4(bbuf + (uint32_t)ks * 32 + b_lane_off, b0, b1, b2, b3);
            mma16816(c[0], a, b0, b1);
            mma16816(c[1], a, b2, b3);
        }

        // ---- register fold into top-8 (rows lane>>2 and lane>>2+8) ----
#pragma unroll
        for (int bn = 0; bn < 2; ++bn) {
            const int cbase = nt * TILE_N + bn * 8 + cb_lane;
            if (c[bn][0] > tvA[7]) top8_insert(c[bn][0], cbase,     tvA, tiA);
            if (c[bn][1] > tvA[7]) top8_insert(c[bn][1], cbase + 1, tvA, tiA);
            if (c[bn][2] > tvB[7]) top8_insert(c[bn][2], cbase,     tvB, tiB);
            if (c[bn][3] > tvB[7]) top8_insert(c[bn][3], cbase + 1, tvB, tiB);
        }

        // ---- ensure tile nt+1 landed (3-deep pipeline: never blocks on
        //      the copy issued THIS iteration unless at the tail) ----
        if (nt + 3 < NTILE)      cp_wait<2>();
        else if (nt + 2 < NTILE) cp_wait<1>();
        else if (nt + 1 < NTILE) cp_wait<0>();
        __syncthreads();
    }

    // ---- merge top-8 across the 4 lanes sharing each token row ----
#pragma unroll
    for (int step = 1; step <= 2; step <<= 1) {
        float ov[8]; int oi[8];
#pragma unroll
        for (int k = 0; k < 8; ++k) {
            ov[k] = __shfl_xor_sync(0xffffffffu, tvA[k], step);
            oi[k] = __shfl_xor_sync(0xffffffffu, tiA[k], step);
        }
#pragma unroll
        for (int k = 0; k < 8; ++k)
            if (ov[k] > tvA[7] || (ov[k] == tvA[7] && oi[k] < tiA[7]))
                top8_insert(ov[k], oi[k], tvA, tiA);
#pragma unroll
        for (int k = 0; k < 8; ++k) {
            ov[k] = __shfl_xor_sync(0xffffffffu, tvB[k], step);
            oi[k] = __shfl_xor_sync(0xffffffffu, tiB[k], step);
        }
#pragma unroll
        for (int k = 0; k < 8; ++k)
            if (ov[k] > tvB[7] || (ov[k] == tvB[7] && oi[k] < tiB[7]))
                top8_insert(ov[k], oi[k], tvB, tiB);
    }
    __syncthreads();   // mainloop done block-wide; smem reusable

    // ---- in-block classification (lane&3 == 0 owns 2 tokens) ----
    if ((lane & 3) == 0) {
        const int r = lane >> 2;
#pragma unroll
        for (int h = 0; h < 2; ++h) {
            const float* tv = h ? tvB : tvA;
            const int*   ti = h ? tiB : tiA;
            int tlocal = wid * 16 + h * 8 + r;
            bc[tlocal] = ti[0];                      // provisional
            if (tv[0] - tv[1] < TAU) {
                if (tv[0] - tv[7] >= TAU) {
                    int p = atomicAdd(&cnt[0], 1);
                    s_fixtok[p] = tlocal;
#pragma unroll
                    for (int k = 0; k < 8; ++k) s_top8c[tlocal * 8 + k] = ti[k];
                } else {
                    int p = atomicAdd(&cnt[1], 1);
                    s_deeptok[p] = tlocal;
                }
            }
        }
    }
    __syncthreads();

    // ---- fix1-type: exact rescore of 8 candidates, SMEM-STAGED chunks ----
    // e-rows at A region (64 x FROWB); x-rows at B slot 0 (8 x FROWB).
    {
        const int nfix = cnt[0];
        float* esm = (float*)(smem + A_OFF);
        float* xsm = (float*)(smem + BBASE_OFF);
        for (int cb2 = 0; cb2 < nfix; cb2 += 8) {
            const int nent = min(8, nfix - cb2);
            for (int i = tid; i < nent * 8 * 64; i += 256) {
                int row = i >> 6;          // 0..63
                int seg = i & 63;
                int code = s_top8c[s_fixtok[cb2 + (row >> 3)] * 8 + (row & 7)];
                cp16(sb + A_OFF + (uint32_t)row * FROWB + (uint32_t)seg * 16,
                     g_en + ((size_t)q * Kc + code) * Dd + seg * 4);
            }
            for (int i = tid; i < nent * 64; i += 256) {
                int row = i >> 6;
                int seg = i & 63;
                cp16(sb + BBASE_OFF + (uint32_t)row * FROWB + (uint32_t)seg * 16,
                     g_xn + (size_t)(tok0 + s_fixtok[cb2 + row]) * Dd + seg * 4);
            }
            cp_commit();
            cp_wait<0>();
            __syncthreads();

            float v = -3.4e38f;
            int   code = 0x7fffffff;
            if (tid < nent * 8) {
                const int e = tid >> 3;
                const int slot = tid & 7;
                code = s_top8c[s_fixtok[cb2 + e] * 8 + slot];
                const float* er = (const float*)((const char*)esm + tid * FROWB);
                const float* xr = (const float*)((const char*)xsm + e * FROWB);
                float acc = 0.f;
#pragma unroll 8
                for (int d = 0; d < Dd; ++d) acc = __fmaf_rn(xr[d], er[d], acc);
                v = acc;
            }
            if (tid < 64) {
#pragma unroll
                for (int o = 4; o; o >>= 1) {
                    float ov = __shfl_down_sync(0xffffffffu, v, o);
                    int   oi = __shfl_down_sync(0xffffffffu, code, o);
                    if (ov > v || (ov == v && oi < code)) { v = ov; code = oi; }
                }
                if ((tid & 7) == 0 && (tid >> 3) < nent)
                    bc[s_fixtok[cb2 + (tid >> 3)]] = code;
            }
            __syncthreads();
        }
    }
    __syncthreads();

    // ---- deep ties (rare): full exact 2048-scan, one token at a time ----
    {
        const int ndeep = cnt[1];
        for (int e = 0; e < ndeep; ++e) {
            const int tl = s_deeptok[e];
            const float* xr = g_xn + (size_t)(tok0 + tl) * Dd;
            float best = -3.4e38f;
            int   bi = 0x7fffffff;
            for (int c0 = tid; c0 < Kc; c0 += 256) {
                const float* er = g_en + ((size_t)q * Kc + c0) * Dd;
                float acc = 0.f;
#pragma unroll 8
                for (int d = 0; d < Dd; ++d) acc = __fmaf_rn(xr[d], er[d], acc);
                if (acc > best) { best = acc; bi = c0; }   // ascending: lowest kept
            }
            s_rv[tid] = best;
            s_ri[tid] = bi;
            __syncthreads();
            if (tid == 0) {
                float v = -3.4e38f;
                int   i = 0x7fffffff;
                for (int t = 0; t < 256; ++t)
                    if (s_rv[t] > v || (s_rv[t] == v && s_ri[t] < i)) {
                        v = s_rv[t]; i = s_ri[t];
                    }
                bc[tl] = i;
            }
            __syncthreads();
        }
    }

    // ---- final outputs: encoding + raw-codeword gather (coalesced) ----
    if (tid < TM) {
        long long epos = (long long)NTOK * Dd + (tok0 + tid);
        if (epos < out_size) out[epos] = (float)bc[tid];
    }
    __syncthreads();
    const float* Eqraw = embed + (size_t)q * Kc * Dd;
    for (int i = tid; i < TM * (Dd / 4); i += 256) {
        int token = i >> 6;
        int r = i & 63;
        int code = bc[token];
        ((float4*)(out + (size_t)(tok0 + token) * Dd))[r] =
            ((const float4*)(Eqraw + (size_t)code * Dd))[r];
    }
}

// ---------------------------------------------------------------------------
// Tail: zero-fill vq_loss (and any slack) past quantized+encoding.
// ---------------------------------------------------------------------------
__global__ void zero_tail(float* __restrict__ out, long long start, long long end) {
    long long i = start + (long long)blockIdx.x * blockDim.x + threadIdx.x;
    if (i < end) out[i] = 0.f;
}

extern "C" void kernel_launch(void* const* d_in, const int* in_sizes, int n_in,
                              void* d_out, int out_size) {
    const float* x     = (const float*)d_in[0];
    const float* embed = (const float*)d_in[1];
    if (n_in >= 2 && in_sizes[0] == Qn * Kc * Dd && in_sizes[1] == NTOK * Dd) {
        const float* t = x; x = embed; embed = t;
    }
    float* out = (float*)d_out;

    l2norm_e_kernel<<<(Qn * Kc) / 8, 256>>>(embed);
    l2norm_x_kernel<<<NTOK / 8, 256>>>(x);

    long long tail = (long long)NTOK * Dd + NTOK;
    if ((long long)out_size > tail) {
        long long n = (long long)out_size - tail;
        int blocks = (int)((n + 255) / 256);
        zero_tail<<<blocks, 256>>>(out, tail, (long long)out_size);
    }

    cudaFuncSetAttribute(pq_mma_kernel, cudaFuncAttributeMaxDynamicSharedMemorySize,
                         SMEM_TOTAL);
    pq_mma_kernel<<<NTOK / TM, 256, SMEM_TOTAL>>>(embed, out, (long long)out_size);
}

// round 16
// speedup vs baseline: 1.0403x; 1.0403x over previous
#include <cuda_runtime.h>
#include <cuda_bf16.h>
#include <cstdint>

// Problem constants
#define Qn 4
#define Kc 2048
#define Dd 256
#define Bb 8
#define Nn 8192
#define NTOK (Bb * Nn)        // 65536 tokens
#define MCHUNK (Nn / Qn)      // 2048 tokens per (b, q) chunk

// Screening GEMM tiling (mma.m16n8k16 bf16 -> f32)
#define TM 64                 // tokens per block (half of before => 3 blocks/SM)
#define TILE_N 32             // codes per tile; warp covers 16 of them
#define NTILE (Kc / TILE_N)   // 64 tiles
#define KSTEPS (Dd / 16)      // 16 k-steps

#define LDMAB 264             // padded leading dim (bf16): 528B rows, conflict-free ldsm
#define ROWB  (LDMAB * 2)     // 528 bytes

#define TAU 2e-3f             // certification margin (~7 sigma of bf16 screen noise)
#define FROWB 1040            // fixup smem row stride (bytes)

// SMEM layout (bytes)
#define CNT_OFF    0                          // int s_nfix, s_ndeep (8 B)
#define A_OFF      128
#define A_BYTES    (TM * ROWB)                // 33792
#define B_BYTES    (TILE_N * ROWB)            // 16896
#define BBASE_OFF  (A_OFF + A_BYTES)          // 33920
#define SMEM_TOTAL (BBASE_OFF + 2 * B_BYTES)  // 67712 => 3 blocks/SM
// Post-loop reuse:
//   merge/classify scratch in B slot 1 (16896 B):
#define T8V_OFF    (BBASE_OFF + B_BYTES)            // float [64][2][8] = 4096
#define T8I_OFF    (T8V_OFF + 4096)                 // int   [64][2][8] = 4096
#define BC_OFF     (T8I_OFF + 4096)                 // int bc[64] = 256
#define FIXTOK_OFF (BC_OFF + 256)                   // int [64] = 256
#define DEEP_OFF   (FIXTOK_OFF + 256)               // int [64] = 256
#define RV_OFF     (DEEP_OFF + 256)                 // float[256] = 1024
#define RI_OFF     (RV_OFF + 1024)                  // int[256] = 1024
//   fix staging: e-rows at A_OFF (32 x FROWB = 33280 <= 33792),
//                x-rows at BBASE_OFF (4 x FROWB = 4160 <= 16896)

// Global scratch (static; no allocs)
__device__ float         g_xn[NTOK * Dd];        // normalized x, fp32 (exact rescore)
__device__ float         g_en[Qn * Kc * Dd];     // normalized embed, fp32 (exact rescore)
__device__ __nv_bfloat16 g_xnb[NTOK * Dd];       // bf16 screen copies
__device__ __nv_bfloat16 g_enb[Qn * Kc * Dd];

// ---------------------------------------------------------------------------
// PTX helpers
// ---------------------------------------------------------------------------
__device__ __forceinline__ void cp16(uint32_t smem_addr, const void* gptr) {
    asm volatile("cp.async.ca.shared.global [%0], [%1], 16;"
                 :: "r"(smem_addr), "l"(gptr));
}
__device__ __forceinline__ void cp_commit() { asm volatile("cp.async.commit_group;"); }
template <int N>
__device__ __forceinline__ void cp_wait() { asm volatile("cp.async.wait_group %0;" :: "n"(N)); }
__device__ __forceinline__ uint32_t smem_u32(const void* p) {
    uint32_t a;
    asm("{ .reg .u64 t; cvta.to.shared.u64 t, %1; cvt.u32.u64 %0, t; }"
        : "=r"(a) : "l"(p));
    return a;
}
__device__ __forceinline__ void ldsm_x4(uint32_t addr, uint32_t& r0, uint32_t& r1,
                                        uint32_t& r2, uint32_t& r3) {
    asm volatile("ldmatrix.sync.aligned.m8n8.x4.shared.b16 {%0,%1,%2,%3}, [%4];"
                 : "=r"(r0), "=r"(r1), "=r"(r2), "=r"(r3) : "r"(addr));
}
__device__ __forceinline__ void mma16816(float* c, const uint32_t* a,
                                         uint32_t b0, uint32_t b1) {
    asm volatile(
        "mma.sync.aligned.m16n8k16.row.col.f32.bf16.bf16.f32 "
        "{%0,%1,%2,%3}, {%4,%5,%6,%7}, {%8,%9}, {%0,%1,%2,%3};"
        : "+f"(c[0]), "+f"(c[1]), "+f"(c[2]), "+f"(c[3])
        : "r"(a[0]), "r"(a[1]), "r"(a[2]), "r"(a[3]), "r"(b0), "r"(b1));
}

// ---------------------------------------------------------------------------
// Kernel 0a/0b: L2 normalize rows, EXACT reference-mimicking fp32 pipeline
// (unfused mul+add, shfl.down tree, sqrt.rn, max 1e-12, div.rn).
// DO NOT CHANGE NUMERICS. Also writes bf16 screen copies.
// ---------------------------------------------------------------------------
__global__ void l2norm_e_kernel(const float* __restrict__ embed) {
    int row  = blockIdx.x * 8 + (threadIdx.x >> 5);
    int lane = threadIdx.x & 31;
    if (row >= Qn * Kc) return;
    const float* r = embed + (size_t)row * Dd;
    float v[8];
    float s = 0.f;
#pragma unroll
    for (int i = 0; i < 8; ++i) {
        v[i] = r[lane + 32 * i];
        s = __fadd_rn(s, __fmul_rn(v[i], v[i]));
    }
#pragma unroll
    for (int o = 16; o; o >>= 1)
        s = __fadd_rn(s, __shfl_down_sync(0xffffffffu, s, o));
    float total = __shfl_sync(0xffffffffu, s, 0);
    float nf = fmaxf(__fsqrt_rn(total), 1e-12f);
#pragma unroll
    for (int i = 0; i < 8; ++i) {
        float nv = __fdiv_rn(v[i], nf);
        size_t idx = (size_t)row * Dd + lane + 32 * i;
        g_en[idx]  = nv;
        g_enb[idx] = __float2bfloat16(nv);
    }
}

__global__ void l2norm_x_kernel(const float* __restrict__ x) {
    int row  = blockIdx.x * 8 + (threadIdx.x >> 5);
    int lane = threadIdx.x & 31;
    if (row >= NTOK) return;
    const float* r = x + (size_t)row * Dd;
    float v[8];
    float s = 0.f;
#pragma unroll
    for (int i = 0; i < 8; ++i) {
        v[i] = r[lane + 32 * i];
        s = __fadd_rn(s, __fmul_rn(v[i], v[i]));
    }
#pragma unroll
    for (int o = 16; o; o >>= 1)
        s = __fadd_rn(s, __shfl_down_sync(0xffffffffu, s, o));
    float total = __shfl_sync(0xffffffffu, s, 0);
    float nf = fmaxf(__fsqrt_rn(total), 1e-12f);
#pragma unroll
    for (int i = 0; i < 8; ++i) {
        float nv = __fdiv_rn(v[i], nf);
        size_t idx = (size_t)row * Dd + lane + 32 * i;
        g_xn[idx]  = nv;
        g_xnb[idx] = __float2bfloat16(nv);
    }
}

// top-8 insertion with (value desc, index asc) ordering
__device__ __forceinline__ void top8_insert(float v, int c, float* tv, int* ti) {
#pragma unroll
    for (int p = 0; p < 8; ++p) {
        bool better = (v > tv[p]) || (v == tv[p] && c < ti[p]);
        if (better) {
            float fv = tv[p]; tv[p] = v; v = fv;
            int   fc = ti[p]; ti[p] = c; c = fc;
        }
    }
}

// ---------------------------------------------------------------------------
// Kernel 1: bf16 mma.sync screening GEMM, TM=64 / 3 blocks/SM (occupancy
// lever). 8 warps = 4 token-groups x 2 code-halves; warp computes the
// VALIDATED 16-token x 16-code inner loop. 64 tiles of 32 codes, 2-slot
// prefetch (R13 structure). Per-warp top-8 halves merged via smem, then
// in-block exact certification (sequential ascending-d __fmaf_rn chains,
// bit-exact vs rounds 4-6).
// ---------------------------------------------------------------------------
__global__ void __launch_bounds__(256, 3)
pq_mma_kernel(const float* __restrict__ embed,
              float* __restrict__ out,
              long long out_size) {
    extern __shared__ char smem[];
    const uint32_t sb = smem_u32(smem);
    int*   cnt       = (int*)(smem + CNT_OFF);      // [0]=nfix, [1]=ndeep
    float* s_t8v     = (float*)(smem + T8V_OFF);    // [64][2][8]
    int*   s_t8i     = (int*)(smem + T8I_OFF);      // [64][2][8]
    int*   bc        = (int*)(smem + BC_OFF);
    int*   s_fixtok  = (int*)(smem + FIXTOK_OFF);
    int*   s_deeptok = (int*)(smem + DEEP_OFF);
    float* s_rv      = (float*)(smem + RV_OFF);
    int*   s_ri      = (int*)(smem + RI_OFF);

    const int tid  = threadIdx.x;
    const int wid  = tid >> 5;
    const int lane = tid & 31;
    const int tg   = wid & 3;          // token group: tokens [tg*16, tg*16+16)
    const int cg   = wid >> 2;         // code half: codes [cg*16, cg*16+16) of tile
    const int tok0 = blockIdx.x * TM;
    const int q = (tok0 % Nn) / MCHUNK;
    const __nv_bfloat16* Eb = g_enb + (size_t)q * Kc * Dd;

    if (tid == 0) { cnt[0] = 0; cnt[1] = 0; }

    // ---- stage A (64 tokens x 256 bf16, 528B rows) + B tile 0 ----
    for (int i = tid; i < TM * 32; i += 256) {
        int row = i >> 5, seg = i & 31;
        cp16(sb + A_OFF + (uint32_t)row * ROWB + (uint32_t)seg * 16,
             g_xnb + (size_t)(tok0 + row) * Dd + seg * 8);
    }
    for (int i = tid; i < TILE_N * 32; i += 256) {
        int row = i >> 5, seg = i & 31;
        cp16(sb + BBASE_OFF + (uint32_t)row * ROWB + (uint32_t)seg * 16,
             Eb + (size_t)row * Dd + seg * 8);
    }
    cp_commit();
    cp_wait<0>();
    __syncthreads();

    // A ldsm per-lane base (validated mapping; token rows tg*16..+16)
    const uint32_t a_base = sb + A_OFF
        + (uint32_t)(tg * 16 + ((lane >> 3) & 1) * 8 + (lane & 7)) * ROWB
        + (uint32_t)((lane >> 4) * 8) * 2;

    // B ldsm per-lane offset within the warp's 16-code half (validated)
    const uint32_t b_lane_off =
        (uint32_t)(cg * 16 + ((lane >> 4) & 1) * 8 + (lane & 7)) * ROWB +
        (uint32_t)(((lane >> 3) & 1) * 8) * 2;

    // per-thread top-8 for two token rows: A = lane>>2, B = lane>>2 + 8
    float tvA[8], tvB[8];
    int   tiA[8], tiB[8];
#pragma unroll
    for (int k = 0; k < 8; ++k) {
        tvA[k] = -3.4e38f; tiA[k] = 0x7fffffff;
        tvB[k] = -3.4e38f; tiB[k] = 0x7fffffff;
    }
    const int cb_lane = (lane & 3) * 2;

    for (int nt = 0; nt < NTILE; ++nt) {
        // prefetch B(nt+1) into the other slot (overlaps compute)
        if (nt + 1 < NTILE) {
            uint32_t dstb = sb + BBASE_OFF + (uint32_t)((nt + 1) & 1) * B_BYTES;
            for (int i = tid; i < TILE_N * 32; i += 256) {
                int row = i >> 5, seg = i & 31;
                cp16(dstb + (uint32_t)row * ROWB + (uint32_t)seg * 16,
                     Eb + (size_t)((nt + 1) * TILE_N + row) * Dd + seg * 8);
            }
            cp_commit();
        }

        // ---- compute: 16 tokens x 16 codes per warp, K=256 ----
        const uint32_t bbuf = sb + BBASE_OFF + (uint32_t)(nt & 1) * B_BYTES;
        float c[2][4];
#pragma unroll
        for (int bn = 0; bn < 2; ++bn)
#pragma unroll
            for (int e = 0; e < 4; ++e) c[bn][e] = 0.f;

#pragma unroll
        for (int ks = 0; ks < KSTEPS; ++ks) {
            uint32_t a[4];
            ldsm_x4(a_base + ks * 32, a[0], a[1], a[2], a[3]);
            uint32_t b0, b1, b2, b3;
            ldsm_x4(bbuf + (uint32_t)ks * 32 + b_lane_off, b0, b1, b2, b3);
            mma16816(c[0], a, b0, b1);
            mma16816(c[1], a, b2, b3);
        }

        // ---- register fold into top-8 (rows lane>>2 and lane>>2+8) ----
#pragma unroll
        for (int bn = 0; bn < 2; ++bn) {
            const int cbase = nt * TILE_N + cg * 16 + bn * 8 + cb_lane;
            if (c[bn][0] > tvA[7]) top8_insert(c[bn][0], cbase,     tvA, tiA);
            if (c[bn][1] > tvA[7]) top8_insert(c[bn][1], cbase + 1, tvA, tiA);
            if (c[bn][2] > tvB[7]) top8_insert(c[bn][2], cbase,     tvB, tiB);
            if (c[bn][3] > tvB[7]) top8_insert(c[bn][3], cbase + 1, tvB, tiB);
        }

        cp_wait<0>();
        __syncthreads();   // B(nt+1) landed; old slot free next iteration
    }

    // ---- merge top-8 across the 4 lanes sharing each token row ----
#pragma unroll
    for (int step = 1; step <= 2; step <<= 1) {
        float ov[8]; int oi[8];
#pragma unroll
        for (int k = 0; k < 8; ++k) {
            ov[k] = __shfl_xor_sync(0xffffffffu, tvA[k], step);
            oi[k] = __shfl_xor_sync(0xffffffffu, tiA[k], step);
        }
#pragma unroll
        for (int k = 0; k < 8; ++k)
            if (ov[k] > tvA[7] || (ov[k] == tvA[7] && oi[k] < tiA[7]))
                top8_insert(ov[k], oi[k], tvA, tiA);
#pragma unroll
        for (int k = 0; k < 8; ++k) {
            ov[k] = __shfl_xor_sync(0xffffffffu, tvB[k], step);
            oi[k] = __shfl_xor_sync(0xffffffffu, tiB[k], step);
        }
#pragma unroll
        for (int k = 0; k < 8; ++k)
            if (ov[k] > tvB[7] || (ov[k] == tvB[7] && oi[k] < tiB[7]))
                top8_insert(ov[k], oi[k], tvB, tiB);
    }
    __syncthreads();   // mainloop done; B slot 1 reusable as scratch

    // ---- publish per-warp (code-half) top-8 lists to smem ----
    if ((lane & 3) == 0) {
        const int r = lane >> 2;
#pragma unroll
        for (int h = 0; h < 2; ++h) {
            const float* tv = h ? tvB : tvA;
            const int*   ti = h ? tiB : tiA;
            int tlocal = tg * 16 + h * 8 + r;
            int base = (tlocal * 2 + cg) * 8;
#pragma unroll
            for (int k = 0; k < 8; ++k) {
                s_t8v[base + k] = tv[k];
                s_t8i[base + k] = ti[k];
            }
        }
    }
    __syncthreads();

    // ---- merge the two code-halves + classify (thread per token) ----
    if (tid < TM) {
        float tv[8]; int ti[8];
        int b0 = (tid * 2 + 0) * 8;
        int b1 = (tid * 2 + 1) * 8;
#pragma unroll
        for (int k = 0; k < 8; ++k) { tv[k] = s_t8v[b0 + k]; ti[k] = s_t8i[b0 + k]; }
#pragma unroll
        for (int k = 0; k < 8; ++k) {
            float v = s_t8v[b1 + k]; int c = s_t8i[b1 + k];
            if (v > tv[7] || (v == tv[7] && c < ti[7])) top8_insert(v, c, tv, ti);
        }
        bc[tid] = ti[0];
        if (tv[0] - tv[1] < TAU) {
            if (tv[0] - tv[7] >= TAU) {
                int p = atomicAdd(&cnt[0], 1);
                s_fixtok[p] = tid;
                int base = (tid * 2 + 0) * 8;   // reuse s_t8i[token][0][*] as top8 store
#pragma unroll
                for (int k = 0; k < 8; ++k) s_t8i[base + k] = ti[k];
            } else {
                int p = atomicAdd(&cnt[1], 1);
                s_deeptok[p] = tid;
            }
        }
    }
    __syncthreads();

    // ---- fix1-type: exact rescore of 8 candidates, SMEM-STAGED chunks of 4 ----
    // e-rows at A region (32 x FROWB = 33280 <= 33792); x-rows at B slot 0.
    {
        const int nfix = cnt[0];
        float* esm = (float*)(smem + A_OFF);
        float* xsm = (float*)(smem + BBASE_OFF);
        for (int cb2 = 0; cb2 < nfix; cb2 += 4) {
            const int nent = min(4, nfix - cb2);
            for (int i = tid; i < nent * 8 * 64; i += 256) {
                int row = i >> 6;          // 0..31
                int seg = i & 63;
                int code = s_t8i[(s_fixtok[cb2 + (row >> 3)] * 2) * 8 + (row & 7)];
                cp16(sb + A_OFF + (uint32_t)row * FROWB + (uint32_t)seg * 16,
                     g_en + ((size_t)q * Kc + code) * Dd + seg * 4);
            }
            for (int i = tid; i < nent * 64; i += 256) {
                int row = i >> 6;
                int seg = i & 63;
                cp16(sb + BBASE_OFF + (uint32_t)row * FROWB + (uint32_t)seg * 16,
                     g_xn + (size_t)(tok0 + s_fixtok[cb2 + row]) * Dd + seg * 4);
            }
            cp_commit();
            cp_wait<0>();
            __syncthreads();

            float v = -3.4e38f;
            int   code = 0x7fffffff;
            if (tid < nent * 8) {
                const int e = tid >> 3;
                const int slot = tid & 7;
                code = s_t8i[(s_fixtok[cb2 + e] * 2) * 8 + slot];
                const float* er = (const float*)((const char*)esm + tid * FROWB);
                const float* xr = (const float*)((const char*)xsm + e * FROWB);
                float acc = 0.f;
#pragma unroll 8
                for (int d = 0; d < Dd; ++d) acc = __fmaf_rn(xr[d], er[d], acc);
                v = acc;
            }
            if (tid < 32) {
#pragma unroll
                for (int o = 4; o; o >>= 1) {
                    float ov = __shfl_down_sync(0xffffffffu, v, o);
                    int   oi = __shfl_down_sync(0xffffffffu, code, o);
                    if (ov > v || (ov == v && oi < code)) { v = ov; code = oi; }
                }
                if ((tid & 7) == 0 && (tid >> 3) < nent)
                    bc[s_fixtok[cb2 + (tid >> 3)]] = code;
            }
            __syncthreads();
        }
    }
    __syncthreads();

    // ---- deep ties (rare): full exact 2048-scan, one token at a time ----
    {
        const int ndeep = cnt[1];
        for (int e = 0; e < ndeep; ++e) {
            const int tl = s_deeptok[e];
            const float* xr = g_xn + (size_t)(tok0 + tl) * Dd;
            float best = -3.4e38f;
            int   bi = 0x7fffffff;
            for (int c0 = tid; c0 < Kc; c0 += 256) {
                const float* er = g_en + ((size_t)q * Kc + c0) * Dd;
                float acc = 0.f;
#pragma unroll 8
                for (int d = 0; d < Dd; ++d) acc = __fmaf_rn(xr[d], er[d], acc);
                if (acc > best) { best = acc; bi = c0; }   // ascending: lowest kept
            }
            s_rv[tid] = best;
            s_ri[tid] = bi;
            __syncthreads();
            if (tid == 0) {
                float v = -3.4e38f;
                int   i = 0x7fffffff;
                for (int t = 0; t < 256; ++t)
                    if (s_rv[t] > v || (s_rv[t] == v && s_ri[t] < i)) {
                        v = s_rv[t]; i = s_ri[t];
                    }
                bc[tl] = i;
            }
            __syncthreads();
        }
    }

    // ---- final outputs: encoding + raw-codeword gather (coalesced) ----
    if (tid < TM) {
        long long epos = (long long)NTOK * Dd + (tok0 + tid);
        if (epos < out_size) out[epos] = (float)bc[tid];
    }
    __syncthreads();
    const float* Eqraw = embed + (size_t)q * Kc * Dd;
    for (int i = tid; i < TM * (Dd / 4); i += 256) {
        int token = i >> 6;
        int r = i & 63;
        int code = bc[token];
        ((float4*)(out + (size_t)(tok0 + token) * Dd))[r] =
            ((const float4*)(Eqraw + (size_t)code * Dd))[r];
    }
}

// ---------------------------------------------------------------------------
// Tail: zero-fill vq_loss (and any slack) past quantized+encoding.
// ---------------------------------------------------------------------------
__global__ void zero_tail(float* __restrict__ out, long long start, long long end) {
    long long i = start + (long long)blockIdx.x * blockDim.x + threadIdx.x;
    if (i < end) out[i] = 0.f;
}

extern "C" void kernel_launch(void* const* d_in, const int* in_sizes, int n_in,
                              void* d_out, int out_size) {
    const float* x     = (const float*)d_in[0];
    const float* embed = (const float*)d_in[1];
    if (n_in >= 2 && in_sizes[0] == Qn * Kc * Dd && in_sizes[1] == NTOK * Dd) {
        const float* t = x; x = embed; embed = t;
    }
    float* out = (float*)d_out;

    l2norm_e_kernel<<<(Qn * Kc) / 8, 256>>>(embed);
    l2norm_x_kernel<<<NTOK / 8, 256>>>(x);

    long long tail = (long long)NTOK * Dd + NTOK;
    if ((long long)out_size > tail) {
        long long n = (long long)out_size - tail;
        int blocks = (int)((n + 255) / 256);
        zero_tail<<<blocks, 256>>>(out, tail, (long long)out_size);
    }

    cudaFuncSetAttribute(pq_mma_kernel, cudaFuncAttributeMaxDynamicSharedMemorySize,
                         SMEM_TOTAL);
    pq_mma_kernel<<<NTOK / TM, 256, SMEM_TOTAL>>>(embed, out, (long long)out_size);
}